// round 11
// baseline (speedup 1.0000x reference)
#include <cuda_runtime.h>
#include <cuda_bf16.h>
#include <cuda_fp16.h>
#include <math.h>
#include <stdint.h>

#define TT 512
#define BB 64
#define DD 1024
#define HH 1024
#define GG 4096
#define NCTA 128

// ---------------------------------------------------------------------------
// Device scratch (allocation-free rules: __device__ globals)
// ---------------------------------------------------------------------------
static __device__ float g_gx[(size_t)TT * BB * GG];            // input gates (+biases)
static __device__ __nv_bfloat16 g_xhi[(size_t)TT * BB * DD];   // x split (phase 1)
static __device__ __nv_bfloat16 g_xlo[(size_t)TT * BB * DD];
static __device__ __nv_bfloat16 g_wihhi[GG * DD];              // w_ih split (phase 1)
static __device__ __nv_bfloat16 g_wihlo[GG * DD];
static __device__ __half g_whh16[GG * HH];                     // w_hh fp16, CTA-tiled rows
static __device__ __half g_h16[2][BB * HH];                    // h fp16 ping-pong
static __device__ unsigned g_arrive = 0;
static __device__ unsigned g_release = 0;

// ---------------------------------------------------------------------------
// Baseline-PTX tensor helpers (sm_80+: compile for plain sm_103)
// ---------------------------------------------------------------------------
__device__ __forceinline__ uint32_t smem_u32(const void* p) {
    uint32_t a;
    asm("{ .reg .u64 t; cvta.to.shared.u64 t, %1; cvt.u32.u64 %0, t; }"
        : "=r"(a) : "l"(p));
    return a;
}
__device__ __forceinline__ void cp16(uint32_t dst, const void* src) {
    asm volatile("cp.async.cg.shared.global [%0], [%1], 16;" :: "r"(dst), "l"(src) : "memory");
}
#define CP_COMMIT() asm volatile("cp.async.commit_group;" ::: "memory")
#define CP_WAIT0()  asm volatile("cp.async.wait_group 0;" ::: "memory")
#define CP_WAIT1()  asm volatile("cp.async.wait_group 1;" ::: "memory")

__device__ __forceinline__ void ldsm4(uint32_t addr, uint32_t* r) {
    asm volatile("ldmatrix.sync.aligned.m8n8.x4.shared.b16 {%0,%1,%2,%3}, [%4];"
                 : "=r"(r[0]), "=r"(r[1]), "=r"(r[2]), "=r"(r[3]) : "r"(addr));
}
__device__ __forceinline__ void mma16816bf(float* c, const uint32_t* a, const uint32_t* b) {
    asm volatile("mma.sync.aligned.m16n8k16.row.col.f32.bf16.bf16.f32 "
                 "{%0,%1,%2,%3}, {%4,%5,%6,%7}, {%8,%9}, {%0,%1,%2,%3};"
                 : "+f"(c[0]), "+f"(c[1]), "+f"(c[2]), "+f"(c[3])
                 : "r"(a[0]), "r"(a[1]), "r"(a[2]), "r"(a[3]), "r"(b[0]), "r"(b[1]));
}
__device__ __forceinline__ void mma16816h(float* c, const uint32_t* a, const uint32_t* b) {
    asm volatile("mma.sync.aligned.m16n8k16.row.col.f32.f16.f16.f32 "
                 "{%0,%1,%2,%3}, {%4,%5,%6,%7}, {%8,%9}, {%0,%1,%2,%3};"
                 : "+f"(c[0]), "+f"(c[1]), "+f"(c[2]), "+f"(c[3])
                 : "r"(a[0]), "r"(a[1]), "r"(a[2]), "r"(a[3]), "r"(b[0]), "r"(b[1]));
}

// ---------------------------------------------------------------------------
// Prep kernels
// ---------------------------------------------------------------------------
__device__ __forceinline__ void split_bf16(float v, __nv_bfloat16* hi, __nv_bfloat16* lo) {
    __nv_bfloat16 h = __float2bfloat16(v);
    *hi = h;
    *lo = __float2bfloat16(v - __bfloat162float(h));
}
__global__ void prep_x_kernel(const float* __restrict__ x) {
    size_t idx = (size_t)blockIdx.x * blockDim.x + threadIdx.x;
    if (idx >= (size_t)TT * BB * DD) return;
    split_bf16(x[idx], &g_xhi[idx], &g_xlo[idx]);
}
__global__ void prep_wih_kernel(const float* __restrict__ w) {
    int idx = blockIdx.x * blockDim.x + threadIdx.x;
    if (idx >= GG * DD) return;
    split_bf16(w[idx], &g_wihhi[idx], &g_wihlo[idx]);
}
// w_hh reorder to fp16: CTA cta owns 32 rows r = g*8+jl <-> in_row = g*1024+cta*8+jl
__global__ void prep_whh_kernel(const float* __restrict__ w) {
    int idx = blockIdx.x * blockDim.x + threadIdx.x;
    if (idx >= GG * HH) return;
    int orow = idx >> 10, k = idx & 1023;
    int cta = orow >> 5, r = orow & 31;
    int g = r >> 3, jl = r & 7;
    int in_row = (g << 10) + (cta << 3) + jl;
    g_whh16[idx] = __float2half(w[(size_t)in_row * HH + k]);
}
__global__ void prep_h_kernel(const float* __restrict__ h0) {
    int idx = blockIdx.x * blockDim.x + threadIdx.x;
    if (idx >= BB * HH) return;
    g_h16[0][idx] = __float2half(h0[idx]);
}

// ---------------------------------------------------------------------------
// Phase 1: gates_x = x @ w_ih^T + b_ih + b_hh  via mma.sync bf16 3-term split.
// (unchanged — proven, fp32-exact to ~1e-7)
// ---------------------------------------------------------------------------
#define P1_STG 10240
#define P1_AHI 0
#define P1_ALO 20480
#define P1_BHI 40960
#define P1_BLO 61440
#define P1_SMEM 81920

__global__ __launch_bounds__(256, 2) void gemm_gx_mma(
    const float* __restrict__ bih, const float* __restrict__ bhh)
{
    extern __shared__ __align__(16) char sm[];
    const uint32_t sb = smem_u32(sm);
    const int tid = threadIdx.x;
    const int wid = tid >> 5, l = tid & 31;
    const int bm = blockIdx.y * 128, bn = blockIdx.x * 128;
    const int wm = wid & 3, wn = wid >> 2;

    const int a_r = wm * 32 + (l & 7) + ((l >> 3) & 1) * 8;
    const int a_cb = ((l >> 4) & 1) * 8;
    const int b_r = wn * 64 + (l & 7) + ((l >> 4) & 1) * 8;
    const int b_cb = ((l >> 3) & 1) * 8;

    float acc[2][8][4];
#pragma unroll
    for (int i = 0; i < 2; i++)
#pragma unroll
        for (int j = 0; j < 8; j++)
#pragma unroll
            for (int q = 0; q < 4; q++) acc[i][j][q] = 0.f;

    const int crow = tid >> 2, cseg = tid & 3;
    auto load_stage = [&](int c, int st) {
        const uint32_t so = st * P1_STG;
        size_t koff = (size_t)c * 32 + cseg * 8;
#pragma unroll
        for (int i = 0; i < 2; i++) {
            int row = crow + i * 64;
            uint32_t sofs = (uint32_t)(row * 80 + cseg * 16);
            cp16(sb + P1_AHI + so + sofs, g_xhi + (size_t)(bm + row) * DD + koff);
            cp16(sb + P1_ALO + so + sofs, g_xlo + (size_t)(bm + row) * DD + koff);
            cp16(sb + P1_BHI + so + sofs, g_wihhi + (size_t)(bn + row) * DD + koff);
            cp16(sb + P1_BLO + so + sofs, g_wihlo + (size_t)(bn + row) * DD + koff);
        }
        CP_COMMIT();
    };

    load_stage(0, 0);

    for (int c = 0; c < 32; c++) {
        if (c < 31) load_stage(c + 1, (c + 1) & 1);
        if (c < 31) { CP_WAIT1(); } else { CP_WAIT0(); }
        __syncthreads();
        const uint32_t so = (c & 1) * P1_STG;
#pragma unroll
        for (int kb = 0; kb < 32; kb += 16) {
            uint32_t ahi[2][4], alo[2][4];
#pragma unroll
            for (int am = 0; am < 2; am++) {
                uint32_t aofs = (uint32_t)((a_r + am * 16) * 80 + (kb + a_cb) * 2);
                ldsm4(sb + P1_AHI + so + aofs, ahi[am]);
                ldsm4(sb + P1_ALO + so + aofs, alo[am]);
            }
#pragma unroll
            for (int bg = 0; bg < 4; bg++) {
                uint32_t bh[4], bl[4];
                uint32_t bofs = (uint32_t)((b_r + bg * 16) * 80 + (kb + b_cb) * 2);
                ldsm4(sb + P1_BHI + so + bofs, bh);
                ldsm4(sb + P1_BLO + so + bofs, bl);
#pragma unroll
                for (int am = 0; am < 2; am++)
#pragma unroll
                    for (int na = 0; na < 2; na++) {
                        float* cc = acc[am][bg * 2 + na];
                        mma16816bf(cc, ahi[am], bh + na * 2);
                        mma16816bf(cc, alo[am], bh + na * 2);
                        mma16816bf(cc, ahi[am], bl + na * 2);
                    }
            }
        }
        __syncthreads();
    }

#pragma unroll
    for (int am = 0; am < 2; am++) {
        int m0 = bm + wm * 32 + am * 16 + (l >> 2);
#pragma unroll
        for (int j = 0; j < 8; j++) {
            int n = bn + wn * 64 + j * 8 + 2 * (l & 3);
            float s0 = bih[n] + bhh[n];
            float s1 = bih[n + 1] + bhh[n + 1];
            float* c = acc[am][j];
            g_gx[(size_t)m0 * GG + n]           = c[0] + s0;
            g_gx[(size_t)m0 * GG + n + 1]       = c[1] + s1;
            g_gx[(size_t)(m0 + 8) * GG + n]     = c[2] + s0;
            g_gx[(size_t)(m0 + 8) * GG + n + 1] = c[3] + s1;
        }
    }
}

// ---------------------------------------------------------------------------
// Phase 2: persistent fp16 recurrence, FULL-h SMEM resident per step.
// 128 CTAs x 512 threads. CTA: D[64 batch x 32 gate-rows], K=1024.
// One cp.async burst loads all 128KB of h -> 2 CTA syncs per step total
// (vs 16 in the chunked version). W (64KB) resident for the whole kernel.
// ---------------------------------------------------------------------------
#define R_SW   0            // 32 rows x 2064B = 66048
#define R_SH   66048        // full h: 64 rows x 2064B = 132096
#define R_SMEM 198144
// sg (2 planes x 64 x 36 floats = 18432 B) aliases h region (post-compute)

__global__ __launch_bounds__(512, 1) void lstm_mma_kernel(
    const float* __restrict__ c0, float* __restrict__ out)
{
    extern __shared__ __align__(16) char sm[];
    const uint32_t sb = smem_u32(sm);
    float* sg = (float*)(sm + R_SH);
    const int tid = threadIdx.x;
    const int wid = tid >> 5, l = tid & 31;
    const int j0 = blockIdx.x * 8;

    const unsigned rel_base = *(volatile unsigned*)&g_release;

    const __half* w16 = g_whh16 + (size_t)blockIdx.x * 32 * HH;

    // ---- Load W into SMEM once: 32 rows x 1024 fp16, row stride 2064B ----
    for (int cid = tid; cid < 4096; cid += 512) {
        int row = cid >> 7, seg = cid & 127;
        uint32_t sofs = (uint32_t)(row * 2064 + seg * 16);
        *(uint4*)(sm + R_SW + sofs) = *(const uint4*)(w16 + (size_t)row * HH + seg * 8);
    }

    // cell state: 1 elem/thread
    const int pb = tid >> 3, pjl = tid & 7;
    float c_reg = c0[(size_t)pb * HH + j0 + pjl];
    __syncthreads();

    // warp geometry: kh = K-half, w8 in 4m x 2n (warp tile m16 x n16)
    const int kh = wid >> 3, w8 = wid & 7;
    const int m0 = (w8 & 3) * 16, n0 = (w8 >> 2) * 16;
    const int a_r = m0 + (l & 7) + ((l >> 3) & 1) * 8;
    const int a_cb = ((l >> 4) & 1) * 8;
    const int b_r = n0 + (l & 7) + ((l >> 4) & 1) * 8;
    const int b_cb = ((l >> 3) & 1) * 8;

    // initial gx prefetch (t = 0)
    float gpre[4];
    {
        const float* gr = g_gx + (size_t)pb * GG + j0 + pjl;
#pragma unroll
        for (int g = 0; g < 4; g++) gpre[g] = gr[g * HH];
    }

    for (int t = 0; t < TT; t++) {
        const __half* h16 = g_h16[t & 1];

        // ---- load ALL of h (64 x 1024 fp16 = 128KB): 16 cp16 per thread ----
#pragma unroll
        for (int i = 0; i < 16; i++) {
            int idx = tid + (i << 9);
            int row = idx >> 7, seg = idx & 127;
            cp16(sb + R_SH + (uint32_t)(row * 2064 + seg * 16),
                 h16 + (size_t)row * HH + seg * 8);
        }
        CP_COMMIT();
        CP_WAIT0();
        __syncthreads();

        // ---- compute: 32 uninterrupted k16 iterations per warp ----
        float acc[2][4];
#pragma unroll
        for (int na = 0; na < 2; na++)
#pragma unroll
            for (int q = 0; q < 4; q++) acc[na][q] = 0.f;

        const int kbase = kh * 512;
#pragma unroll 4
        for (int kk = 0; kk < 512; kk += 16) {
            const int k = kbase + kk;
            uint32_t ah[4], bh[4];
            ldsm4(sb + R_SH + (uint32_t)(a_r * 2064 + (k + a_cb) * 2), ah);
            ldsm4(sb + R_SW + (uint32_t)(b_r * 2064 + (k + b_cb) * 2), bh);
#pragma unroll
            for (int na = 0; na < 2; na++)
                mma16816h(acc[na], ah, bh + na * 2);
        }
        __syncthreads();   // all ldsm done before sg aliases h region

        // prefetch next step's gx (hides DRAM latency under epilogue+barrier)
        float gnext[4];
        if (t < TT - 1) {
            const float* gr = g_gx + (size_t)(t + 1) * BB * GG
                              + (size_t)pb * GG + j0 + pjl;
#pragma unroll
            for (int g = 0; g < 4; g++) gnext[g] = gr[g * HH];
        }

        // stage partial D planes to SMEM (plane kh)
        {
            float* sgp = sg + kh * (64 * 36);
            int m = m0 + (l >> 2);
#pragma unroll
            for (int na = 0; na < 2; na++) {
                int n = n0 + na * 8 + 2 * (l & 3);
                *(float2*)&sgp[m * 36 + n]       = make_float2(acc[na][0], acc[na][1]);
                *(float2*)&sgp[(m + 8) * 36 + n] = make_float2(acc[na][2], acc[na][3]);
            }
        }
        __syncthreads();

        // pointwise LSTM cell: 1 elem/thread
        float* h_out = out + (size_t)t * BB * HH;
        __half* nh16 = g_h16[(t + 1) & 1];
        {
            const float* s0 = sg + pb * 36;
            const float* s1 = sg + 64 * 36 + pb * 36;
            float gi = s0[pjl]      + s1[pjl]      + gpre[0];
            float gf = s0[8 + pjl]  + s1[8 + pjl]  + gpre[1];
            float gg = s0[16 + pjl] + s1[16 + pjl] + gpre[2];
            float go = s0[24 + pjl] + s1[24 + pjl] + gpre[3];
            float ig = 1.0f / (1.0f + __expf(-gi));
            float fg = 1.0f / (1.0f + __expf(-gf));
            float gv = tanhf(gg);
            float og = 1.0f / (1.0f + __expf(-go));
            float cn = fg * c_reg + ig * gv;
            float hn = og * tanhf(cn);
            c_reg = cn;
            size_t hoff = (size_t)pb * HH + j0 + pjl;
            h_out[hoff] = hn;
            nh16[hoff] = __float2half(hn);
            if (t == TT - 1) {
                out[(size_t)TT * BB * HH + hoff] = hn;
                out[(size_t)TT * BB * HH + BB * HH + hoff] = cn;
            }
        }
#pragma unroll
        for (int g = 0; g < 4; g++) gpre[g] = gnext[g];

        // grid-wide barrier (monotonic release, replay-safe)
        if (t < TT - 1) {
            __threadfence();
            __syncthreads();
            if (tid == 0) {
                unsigned target = rel_base + (unsigned)(t + 1);
                unsigned old = atomicAdd(&g_arrive, 1);
                if (old == NCTA - 1) {
                    g_arrive = 0;
                    __threadfence();
                    *(volatile unsigned*)&g_release = target;
                }
            }
            {
                unsigned target = rel_base + (unsigned)(t + 1);
                if (l == 0) {
                    while ((int)(*(volatile unsigned*)&g_release - target) < 0) {}
                }
                __syncwarp();
                __threadfence();
            }
        }
    }
}

extern "C" void kernel_launch(void* const* d_in, const int* in_sizes, int n_in,
                              void* d_out, int out_size)
{
    const float* x    = (const float*)d_in[0];
    const float* h0   = (const float*)d_in[1];
    const float* c0   = (const float*)d_in[2];
    const float* w_ih = (const float*)d_in[3];
    const float* b_ih = (const float*)d_in[4];
    const float* w_hh = (const float*)d_in[5];
    const float* b_hh = (const float*)d_in[6];
    float* out = (float*)d_out;
    (void)in_sizes; (void)n_in; (void)out_size;

    // Prep
    prep_x_kernel<<<(int)(((size_t)TT * BB * DD + 255) / 256), 256>>>(x);
    prep_wih_kernel<<<(GG * DD + 255) / 256, 256>>>(w_ih);
    prep_whh_kernel<<<(GG * HH + 255) / 256, 256>>>(w_hh);
    prep_h_kernel<<<(BB * HH + 255) / 256, 256>>>(h0);

    // Phase 1: input projection on tensor cores (3-term bf16, fp32-exact-ish)
    cudaFuncSetAttribute(gemm_gx_mma,
                         cudaFuncAttributeMaxDynamicSharedMemorySize, P1_SMEM);
    dim3 g1(GG / 128, (TT * BB) / 128);
    gemm_gx_mma<<<g1, 256, P1_SMEM>>>(b_ih, b_hh);

    // Phase 2: persistent fp16 recurrence, full-h SMEM per step
    cudaFuncSetAttribute(lstm_mma_kernel,
                         cudaFuncAttributeMaxDynamicSharedMemorySize, R_SMEM);
    lstm_mma_kernel<<<NCTA, 512, R_SMEM>>>(c0, out);
}

// round 12
// speedup vs baseline: 1.2727x; 1.2727x over previous
#include <cuda_runtime.h>
#include <cuda_bf16.h>
#include <cuda_fp16.h>
#include <math.h>
#include <stdint.h>

#define TT 512
#define BB 64
#define DD 1024
#define HH 1024
#define GG 4096
#define NCTA 128

// ---------------------------------------------------------------------------
// Device scratch (allocation-free rules: __device__ globals)
// ---------------------------------------------------------------------------
static __device__ float g_gx[(size_t)TT * BB * GG];        // input gates (+biases)
static __device__ __half g_x16[(size_t)TT * BB * DD];      // x fp16 (phase 1)
static __device__ __half g_wih16[GG * DD];                 // w_ih fp16 (phase 1)
static __device__ __half g_whh16[GG * HH];                 // w_hh fp16, CTA-tiled rows
static __device__ __half g_h16[2][BB * HH];                // h fp16 ping-pong
static __device__ unsigned g_arrive = 0;
static __device__ unsigned g_release = 0;

// ---------------------------------------------------------------------------
// Baseline-PTX tensor helpers (sm_80+: compile for plain sm_103)
// ---------------------------------------------------------------------------
__device__ __forceinline__ uint32_t smem_u32(const void* p) {
    uint32_t a;
    asm("{ .reg .u64 t; cvta.to.shared.u64 t, %1; cvt.u32.u64 %0, t; }"
        : "=r"(a) : "l"(p));
    return a;
}
__device__ __forceinline__ void cp16(uint32_t dst, const void* src) {
    asm volatile("cp.async.cg.shared.global [%0], [%1], 16;" :: "r"(dst), "l"(src) : "memory");
}
#define CP_COMMIT() asm volatile("cp.async.commit_group;" ::: "memory")
#define CP_WAIT0()  asm volatile("cp.async.wait_group 0;" ::: "memory")
#define CP_WAIT1()  asm volatile("cp.async.wait_group 1;" ::: "memory")

// compile-time-resolved wait (used inside fully unrolled loops)
__device__ __forceinline__ void cp_wait_dyn(int n) {
    switch (n) {
    case 0: asm volatile("cp.async.wait_group 0;" ::: "memory"); break;
    case 1: asm volatile("cp.async.wait_group 1;" ::: "memory"); break;
    case 2: asm volatile("cp.async.wait_group 2;" ::: "memory"); break;
    case 3: asm volatile("cp.async.wait_group 3;" ::: "memory"); break;
    case 4: asm volatile("cp.async.wait_group 4;" ::: "memory"); break;
    case 5: asm volatile("cp.async.wait_group 5;" ::: "memory"); break;
    case 6: asm volatile("cp.async.wait_group 6;" ::: "memory"); break;
    default: asm volatile("cp.async.wait_group 7;" ::: "memory"); break;
    }
}

__device__ __forceinline__ void ldsm4(uint32_t addr, uint32_t* r) {
    asm volatile("ldmatrix.sync.aligned.m8n8.x4.shared.b16 {%0,%1,%2,%3}, [%4];"
                 : "=r"(r[0]), "=r"(r[1]), "=r"(r[2]), "=r"(r[3]) : "r"(addr));
}
__device__ __forceinline__ void mma16816h(float* c, const uint32_t* a, const uint32_t* b) {
    asm volatile("mma.sync.aligned.m16n8k16.row.col.f32.f16.f16.f32 "
                 "{%0,%1,%2,%3}, {%4,%5,%6,%7}, {%8,%9}, {%0,%1,%2,%3};"
                 : "+f"(c[0]), "+f"(c[1]), "+f"(c[2]), "+f"(c[3])
                 : "r"(a[0]), "r"(a[1]), "r"(a[2]), "r"(a[3]), "r"(b[0]), "r"(b[1]));
}

// ---------------------------------------------------------------------------
// Prep kernels
// ---------------------------------------------------------------------------
__global__ void prep_x_kernel(const float* __restrict__ x) {
    size_t idx = (size_t)blockIdx.x * blockDim.x + threadIdx.x;
    if (idx >= (size_t)TT * BB * DD) return;
    g_x16[idx] = __float2half(x[idx]);
}
__global__ void prep_wih_kernel(const float* __restrict__ w) {
    int idx = blockIdx.x * blockDim.x + threadIdx.x;
    if (idx >= GG * DD) return;
    g_wih16[idx] = __float2half(w[idx]);
}
// w_hh reorder to fp16: CTA cta owns 32 rows r = g*8+jl <-> in_row = g*1024+cta*8+jl
__global__ void prep_whh_kernel(const float* __restrict__ w) {
    int idx = blockIdx.x * blockDim.x + threadIdx.x;
    if (idx >= GG * HH) return;
    int orow = idx >> 10, k = idx & 1023;
    int cta = orow >> 5, r = orow & 31;
    int g = r >> 3, jl = r & 7;
    int in_row = (g << 10) + (cta << 3) + jl;
    g_whh16[idx] = __float2half(w[(size_t)in_row * HH + k]);
}
__global__ void prep_h_kernel(const float* __restrict__ h0) {
    int idx = blockIdx.x * blockDim.x + threadIdx.x;
    if (idx >= BB * HH) return;
    g_h16[0][idx] = __float2half(h0[idx]);
}

// ---------------------------------------------------------------------------
// Phase 1: gates_x = x @ w_ih^T + b_ih + b_hh  via mma.sync fp16 single-term.
// Tiles 128x128x32, cp.async double-buffered. Warp grid 4m x 2n (m32 x n64).
// ---------------------------------------------------------------------------
#define P1_STG 10240      // 128 rows x 80B
#define P1_A 0
#define P1_B 20480
#define P1_SMEM 40960

__global__ __launch_bounds__(256, 2) void gemm_gx_mma(
    const float* __restrict__ bih, const float* __restrict__ bhh)
{
    extern __shared__ __align__(16) char sm[];
    const uint32_t sb = smem_u32(sm);
    const int tid = threadIdx.x;
    const int wid = tid >> 5, l = tid & 31;
    const int bm = blockIdx.y * 128, bn = blockIdx.x * 128;
    const int wm = wid & 3, wn = wid >> 2;

    const int a_r = wm * 32 + (l & 7) + ((l >> 3) & 1) * 8;
    const int a_cb = ((l >> 4) & 1) * 8;
    const int b_r = wn * 64 + (l & 7) + ((l >> 4) & 1) * 8;
    const int b_cb = ((l >> 3) & 1) * 8;

    float acc[2][8][4];
#pragma unroll
    for (int i = 0; i < 2; i++)
#pragma unroll
        for (int j = 0; j < 8; j++)
#pragma unroll
            for (int q = 0; q < 4; q++) acc[i][j][q] = 0.f;

    auto load_stage = [&](int c, int st) {
        const uint32_t so = st * P1_STG;
        size_t koff = (size_t)c * 32;
#pragma unroll
        for (int i = 0; i < 2; i++) {
            int idx = tid + (i << 8);
            int row = idx >> 2, seg = idx & 3;
            uint32_t sofs = (uint32_t)(row * 80 + seg * 16);
            cp16(sb + P1_A + so + sofs, g_x16 + (size_t)(bm + row) * DD + koff + seg * 8);
            cp16(sb + P1_B + so + sofs, g_wih16 + (size_t)(bn + row) * DD + koff + seg * 8);
        }
        CP_COMMIT();
    };

    load_stage(0, 0);

    for (int c = 0; c < 32; c++) {
        if (c < 31) load_stage(c + 1, (c + 1) & 1);
        if (c < 31) { CP_WAIT1(); } else { CP_WAIT0(); }
        __syncthreads();
        const uint32_t so = (c & 1) * P1_STG;
#pragma unroll
        for (int kb = 0; kb < 32; kb += 16) {
            uint32_t a0[4], a1[4];
            {
                uint32_t aofs = (uint32_t)((a_r) * 80 + (kb + a_cb) * 2);
                ldsm4(sb + P1_A + so + aofs, a0);
                ldsm4(sb + P1_A + so + aofs + 16 * 80, a1);
            }
#pragma unroll
            for (int bg = 0; bg < 4; bg++) {
                uint32_t bh[4];
                uint32_t bofs = (uint32_t)((b_r + bg * 16) * 80 + (kb + b_cb) * 2);
                ldsm4(sb + P1_B + so + bofs, bh);
#pragma unroll
                for (int na = 0; na < 2; na++) {
                    mma16816h(acc[0][bg * 2 + na], a0, bh + na * 2);
                    mma16816h(acc[1][bg * 2 + na], a1, bh + na * 2);
                }
            }
        }
        __syncthreads();
    }

#pragma unroll
    for (int am = 0; am < 2; am++) {
        int m0 = bm + wm * 32 + am * 16 + (l >> 2);
#pragma unroll
        for (int j = 0; j < 8; j++) {
            int n = bn + wn * 64 + j * 8 + 2 * (l & 3);
            float s0 = bih[n] + bhh[n];
            float s1 = bih[n + 1] + bhh[n + 1];
            float* c = acc[am][j];
            g_gx[(size_t)m0 * GG + n]           = c[0] + s0;
            g_gx[(size_t)m0 * GG + n + 1]       = c[1] + s1;
            g_gx[(size_t)(m0 + 8) * GG + n]     = c[2] + s0;
            g_gx[(size_t)(m0 + 8) * GG + n + 1] = c[3] + s1;
        }
    }
}

// ---------------------------------------------------------------------------
// Phase 2: persistent fp16 recurrence: burst-issue 8 chunk loads (8 groups),
// drain incrementally with wait_group(7-c); ONE sync per chunk (8 distinct
// stage buffers -> no WAR hazard within a step).
// 128 CTAs x 512 threads. CTA: D[64 batch x 32 gate-rows], K=1024.
// ---------------------------------------------------------------------------
#define R_SW   0            // 32 rows x 2064B = 66048
#define R_SH   66048        // 8 stages x 17408B = 139264
#define R_HSTG 17408
#define R_SMEM 205312
// sg (2 planes x 64 x 36 floats = 18432B) aliases stages 0-1 (read only in
// chunks 0-1; all warps are past chunk-2 sync before any sg write)

__global__ __launch_bounds__(512, 1) void lstm_mma_kernel(
    const float* __restrict__ c0, float* __restrict__ out)
{
    extern __shared__ __align__(16) char sm[];
    const uint32_t sb = smem_u32(sm);
    float* sg = (float*)(sm + R_SH);
    const int tid = threadIdx.x;
    const int wid = tid >> 5, l = tid & 31;
    const int j0 = blockIdx.x * 8;

    const unsigned rel_base = *(volatile unsigned*)&g_release;

    const __half* w16 = g_whh16 + (size_t)blockIdx.x * 32 * HH;

    // ---- Load W into SMEM once: 32 rows x 1024 fp16, row stride 2064B ----
    for (int cid = tid; cid < 4096; cid += 512) {
        int row = cid >> 7, seg = cid & 127;
        uint32_t sofs = (uint32_t)(row * 2064 + seg * 16);
        *(uint4*)(sm + R_SW + sofs) = *(const uint4*)(w16 + (size_t)row * HH + seg * 8);
    }

    // cell state: 1 elem/thread
    const int pb = tid >> 3, pjl = tid & 7;
    float c_reg = c0[(size_t)pb * HH + j0 + pjl];
    __syncthreads();

    // warp geometry: kh = K-half, w8 in 4m x 2n (warp tile m16 x n16)
    const int kh = wid >> 3, w8 = wid & 7;
    const int m0 = (w8 & 3) * 16, n0 = (w8 >> 2) * 16;
    const int a_r = m0 + (l & 7) + ((l >> 3) & 1) * 8;
    const int a_cb = ((l >> 4) & 1) * 8;
    const int b_r = n0 + (l & 7) + ((l >> 4) & 1) * 8;
    const int b_cb = ((l >> 3) & 1) * 8;

    const int hrow = tid >> 3, hseg = tid & 7;   // per chunk: 2 cp16/thread

    // initial gx prefetch (t = 0)
    float gpre[4];
    {
        const float* gr = g_gx + (size_t)pb * GG + j0 + pjl;
#pragma unroll
        for (int g = 0; g < 4; g++) gpre[g] = gr[g * HH];
    }

    for (int t = 0; t < TT; t++) {
        const __half* h16 = g_h16[t & 1];

        // ---- burst-issue all 8 chunk loads (one commit group per chunk) ----
#pragma unroll
        for (int c = 0; c < 8; c++) {
            const uint32_t so = R_SH + c * R_HSTG;
            const size_t base2 = (size_t)hrow * HH + c * 128;
#pragma unroll
            for (int i = 0; i < 2; i++) {
                int seg = hseg + i * 8;
                cp16(sb + so + (uint32_t)(hrow * 272 + seg * 16),
                     h16 + base2 + seg * 8);
            }
            CP_COMMIT();
        }

        float acc[2][4];
#pragma unroll
        for (int na = 0; na < 2; na++)
#pragma unroll
            for (int q = 0; q < 4; q++) acc[na][q] = 0.f;

        // ---- drain + compute: one sync per chunk ----
#pragma unroll
        for (int c = 0; c < 8; c++) {
            cp_wait_dyn(7 - c);
            __syncthreads();
            const uint32_t so = R_SH + c * R_HSTG;
#pragma unroll
            for (int kk = 0; kk < 64; kk += 16) {
                const int kb = kh * 64 + kk;
                uint32_t ah[4], bh[4];
                ldsm4(sb + so + (uint32_t)(a_r * 272 + (kb + a_cb) * 2), ah);
                ldsm4(sb + R_SW + (uint32_t)(b_r * 2064 + (c * 128 + kb + b_cb) * 2), bh);
#pragma unroll
                for (int na = 0; na < 2; na++)
                    mma16816h(acc[na], ah, bh + na * 2);
            }
        }

        // prefetch next step's gx (hides DRAM latency under epilogue+barrier)
        float gnext[4];
        if (t < TT - 1) {
            const float* gr = g_gx + (size_t)(t + 1) * BB * GG
                              + (size_t)pb * GG + j0 + pjl;
#pragma unroll
            for (int g = 0; g < 4; g++) gnext[g] = gr[g * HH];
        }

        // stage partial D planes to SMEM (plane kh); safe without extra sync:
        // sg aliases stages 0-1, last read at chunks 0-1, and every thread
        // writing has passed the chunk-7 sync (=> all warps past chunk 2).
        {
            float* sgp = sg + kh * (64 * 36);
            int m = m0 + (l >> 2);
#pragma unroll
            for (int na = 0; na < 2; na++) {
                int n = n0 + na * 8 + 2 * (l & 3);
                *(float2*)&sgp[m * 36 + n]       = make_float2(acc[na][0], acc[na][1]);
                *(float2*)&sgp[(m + 8) * 36 + n] = make_float2(acc[na][2], acc[na][3]);
            }
        }
        __syncthreads();

        // pointwise LSTM cell: 1 elem/thread
        float* h_out = out + (size_t)t * BB * HH;
        __half* nh16 = g_h16[(t + 1) & 1];
        {
            const float* s0 = sg + pb * 36;
            const float* s1 = sg + 64 * 36 + pb * 36;
            float gi = s0[pjl]      + s1[pjl]      + gpre[0];
            float gf = s0[8 + pjl]  + s1[8 + pjl]  + gpre[1];
            float gg = s0[16 + pjl] + s1[16 + pjl] + gpre[2];
            float go = s0[24 + pjl] + s1[24 + pjl] + gpre[3];
            float ig = 1.0f / (1.0f + __expf(-gi));
            float fg = 1.0f / (1.0f + __expf(-gf));
            float gv = tanhf(gg);
            float og = 1.0f / (1.0f + __expf(-go));
            float cn = fg * c_reg + ig * gv;
            float hn = og * tanhf(cn);
            c_reg = cn;
            size_t hoff = (size_t)pb * HH + j0 + pjl;
            h_out[hoff] = hn;
            nh16[hoff] = __float2half(hn);
            if (t == TT - 1) {
                out[(size_t)TT * BB * HH + hoff] = hn;
                out[(size_t)TT * BB * HH + BB * HH + hoff] = cn;
            }
        }
#pragma unroll
        for (int g = 0; g < 4; g++) gpre[g] = gnext[g];

        // grid-wide barrier (monotonic release, replay-safe)
        if (t < TT - 1) {
            __threadfence();
            __syncthreads();
            if (tid == 0) {
                unsigned target = rel_base + (unsigned)(t + 1);
                unsigned old = atomicAdd(&g_arrive, 1);
                if (old == NCTA - 1) {
                    g_arrive = 0;
                    __threadfence();
                    *(volatile unsigned*)&g_release = target;
                }
            }
            {
                unsigned target = rel_base + (unsigned)(t + 1);
                if (l == 0) {
                    while ((int)(*(volatile unsigned*)&g_release - target) < 0) {}
                }
                __syncwarp();
                __threadfence();
            }
        }
    }
}

extern "C" void kernel_launch(void* const* d_in, const int* in_sizes, int n_in,
                              void* d_out, int out_size)
{
    const float* x    = (const float*)d_in[0];
    const float* h0   = (const float*)d_in[1];
    const float* c0   = (const float*)d_in[2];
    const float* w_ih = (const float*)d_in[3];
    const float* b_ih = (const float*)d_in[4];
    const float* w_hh = (const float*)d_in[5];
    const float* b_hh = (const float*)d_in[6];
    float* out = (float*)d_out;
    (void)in_sizes; (void)n_in; (void)out_size;

    // Prep
    prep_x_kernel<<<(int)(((size_t)TT * BB * DD + 255) / 256), 256>>>(x);
    prep_wih_kernel<<<(GG * DD + 255) / 256, 256>>>(w_ih);
    prep_whh_kernel<<<(GG * HH + 255) / 256, 256>>>(w_hh);
    prep_h_kernel<<<(BB * HH + 255) / 256, 256>>>(h0);

    // Phase 1: input projection on tensor cores (fp16 single-term)
    cudaFuncSetAttribute(gemm_gx_mma,
                         cudaFuncAttributeMaxDynamicSharedMemorySize, P1_SMEM);
    dim3 g1(GG / 128, (TT * BB) / 128);
    gemm_gx_mma<<<g1, 256, P1_SMEM>>>(b_ih, b_hh);

    // Phase 2: persistent fp16 recurrence (burst + incremental drain)
    cudaFuncSetAttribute(lstm_mma_kernel,
                         cudaFuncAttributeMaxDynamicSharedMemorySize, R_SMEM);
    lstm_mma_kernel<<<NCTA, 512, R_SMEM>>>(c0, out);
}

// round 13
// speedup vs baseline: 1.3405x; 1.0533x over previous
#include <cuda_runtime.h>
#include <cuda_bf16.h>
#include <cuda_fp16.h>
#include <math.h>
#include <stdint.h>

#define TT 512
#define BB 64
#define DD 1024
#define HH 1024
#define GG 4096
#define NCTA 128

// ---------------------------------------------------------------------------
// Device scratch (allocation-free rules: __device__ globals)
// ---------------------------------------------------------------------------
static __device__ float g_gx[(size_t)TT * BB * GG];        // input gates (+biases)
static __device__ __half g_x16[(size_t)TT * BB * DD];      // x fp16 (phase 1)
static __device__ __half g_wih16[GG * DD];                 // w_ih fp16 (phase 1)
static __device__ __half g_whh16[GG * HH];                 // w_hh fp16, CTA-tiled rows
static __device__ __half g_h16[2][BB * HH];                // h fp16 ping-pong
static __device__ unsigned g_cnt[8];                       // per-group arrive counters (monotonic)
static __device__ unsigned g_rel[8];                       // per-group release words (monotonic)

// ---------------------------------------------------------------------------
// Baseline-PTX tensor helpers (sm_80+: compile for plain sm_103)
// ---------------------------------------------------------------------------
__device__ __forceinline__ uint32_t smem_u32(const void* p) {
    uint32_t a;
    asm("{ .reg .u64 t; cvta.to.shared.u64 t, %1; cvt.u32.u64 %0, t; }"
        : "=r"(a) : "l"(p));
    return a;
}
__device__ __forceinline__ void cp16(uint32_t dst, const void* src) {
    asm volatile("cp.async.cg.shared.global [%0], [%1], 16;" :: "r"(dst), "l"(src) : "memory");
}
#define CP_COMMIT() asm volatile("cp.async.commit_group;" ::: "memory")
#define CP_WAIT0()  asm volatile("cp.async.wait_group 0;" ::: "memory")
#define CP_WAIT1()  asm volatile("cp.async.wait_group 1;" ::: "memory")

// compile-time-resolved wait (used inside fully unrolled loops)
__device__ __forceinline__ void cp_wait_dyn(int n) {
    switch (n) {
    case 0: asm volatile("cp.async.wait_group 0;" ::: "memory"); break;
    case 1: asm volatile("cp.async.wait_group 1;" ::: "memory"); break;
    case 2: asm volatile("cp.async.wait_group 2;" ::: "memory"); break;
    case 3: asm volatile("cp.async.wait_group 3;" ::: "memory"); break;
    case 4: asm volatile("cp.async.wait_group 4;" ::: "memory"); break;
    case 5: asm volatile("cp.async.wait_group 5;" ::: "memory"); break;
    case 6: asm volatile("cp.async.wait_group 6;" ::: "memory"); break;
    default: asm volatile("cp.async.wait_group 7;" ::: "memory"); break;
    }
}

__device__ __forceinline__ void ldsm4(uint32_t addr, uint32_t* r) {
    asm volatile("ldmatrix.sync.aligned.m8n8.x4.shared.b16 {%0,%1,%2,%3}, [%4];"
                 : "=r"(r[0]), "=r"(r[1]), "=r"(r[2]), "=r"(r[3]) : "r"(addr));
}
__device__ __forceinline__ void mma16816h(float* c, const uint32_t* a, const uint32_t* b) {
    asm volatile("mma.sync.aligned.m16n8k16.row.col.f32.f16.f16.f32 "
                 "{%0,%1,%2,%3}, {%4,%5,%6,%7}, {%8,%9}, {%0,%1,%2,%3};"
                 : "+f"(c[0]), "+f"(c[1]), "+f"(c[2]), "+f"(c[3])
                 : "r"(a[0]), "r"(a[1]), "r"(a[2]), "r"(a[3]), "r"(b[0]), "r"(b[1]));
}
__device__ __forceinline__ unsigned flag_acq(const unsigned* p) {
    unsigned v;
    asm volatile("ld.acquire.gpu.global.u32 %0, [%1];" : "=r"(v) : "l"(p) : "memory");
    return v;
}
__device__ __forceinline__ void flag_rel(unsigned* p, unsigned v) {
    asm volatile("st.release.gpu.global.u32 [%0], %1;" :: "l"(p), "r"(v) : "memory");
}

// ---------------------------------------------------------------------------
// Prep kernels
// ---------------------------------------------------------------------------
__global__ void prep_x_kernel(const float* __restrict__ x) {
    size_t idx = (size_t)blockIdx.x * blockDim.x + threadIdx.x;
    if (idx >= (size_t)TT * BB * DD) return;
    g_x16[idx] = __float2half(x[idx]);
}
__global__ void prep_wih_kernel(const float* __restrict__ w) {
    int idx = blockIdx.x * blockDim.x + threadIdx.x;
    if (idx >= GG * DD) return;
    g_wih16[idx] = __float2half(w[idx]);
}
// w_hh reorder to fp16: CTA cta owns 32 rows r = g*8+jl <-> in_row = g*1024+cta*8+jl
__global__ void prep_whh_kernel(const float* __restrict__ w) {
    int idx = blockIdx.x * blockDim.x + threadIdx.x;
    if (idx >= GG * HH) return;
    int orow = idx >> 10, k = idx & 1023;
    int cta = orow >> 5, r = orow & 31;
    int g = r >> 3, jl = r & 7;
    int in_row = (g << 10) + (cta << 3) + jl;
    g_whh16[idx] = __float2half(w[(size_t)in_row * HH + k]);
}
__global__ void prep_h_kernel(const float* __restrict__ h0) {
    int idx = blockIdx.x * blockDim.x + threadIdx.x;
    if (idx >= BB * HH) return;
    g_h16[0][idx] = __float2half(h0[idx]);
}

// ---------------------------------------------------------------------------
// Phase 1: gates_x = x @ w_ih^T + b_ih + b_hh  via mma.sync fp16 single-term.
// Tiles 128x128x32, cp.async double-buffered. Warp grid 4m x 2n (m32 x n64).
// ---------------------------------------------------------------------------
#define P1_STG 10240      // 128 rows x 80B
#define P1_A 0
#define P1_B 20480
#define P1_SMEM 40960

__global__ __launch_bounds__(256, 2) void gemm_gx_mma(
    const float* __restrict__ bih, const float* __restrict__ bhh)
{
    extern __shared__ __align__(16) char sm[];
    const uint32_t sb = smem_u32(sm);
    const int tid = threadIdx.x;
    const int wid = tid >> 5, l = tid & 31;
    const int bm = blockIdx.y * 128, bn = blockIdx.x * 128;
    const int wm = wid & 3, wn = wid >> 2;

    const int a_r = wm * 32 + (l & 7) + ((l >> 3) & 1) * 8;
    const int a_cb = ((l >> 4) & 1) * 8;
    const int b_r = wn * 64 + (l & 7) + ((l >> 4) & 1) * 8;
    const int b_cb = ((l >> 3) & 1) * 8;

    float acc[2][8][4];
#pragma unroll
    for (int i = 0; i < 2; i++)
#pragma unroll
        for (int j = 0; j < 8; j++)
#pragma unroll
            for (int q = 0; q < 4; q++) acc[i][j][q] = 0.f;

    auto load_stage = [&](int c, int st) {
        const uint32_t so = st * P1_STG;
        size_t koff = (size_t)c * 32;
#pragma unroll
        for (int i = 0; i < 2; i++) {
            int idx = tid + (i << 8);
            int row = idx >> 2, seg = idx & 3;
            uint32_t sofs = (uint32_t)(row * 80 + seg * 16);
            cp16(sb + P1_A + so + sofs, g_x16 + (size_t)(bm + row) * DD + koff + seg * 8);
            cp16(sb + P1_B + so + sofs, g_wih16 + (size_t)(bn + row) * DD + koff + seg * 8);
        }
        CP_COMMIT();
    };

    load_stage(0, 0);

    for (int c = 0; c < 32; c++) {
        if (c < 31) load_stage(c + 1, (c + 1) & 1);
        if (c < 31) { CP_WAIT1(); } else { CP_WAIT0(); }
        __syncthreads();
        const uint32_t so = (c & 1) * P1_STG;
#pragma unroll
        for (int kb = 0; kb < 32; kb += 16) {
            uint32_t a0[4], a1[4];
            {
                uint32_t aofs = (uint32_t)((a_r) * 80 + (kb + a_cb) * 2);
                ldsm4(sb + P1_A + so + aofs, a0);
                ldsm4(sb + P1_A + so + aofs + 16 * 80, a1);
            }
#pragma unroll
            for (int bg = 0; bg < 4; bg++) {
                uint32_t bh[4];
                uint32_t bofs = (uint32_t)((b_r + bg * 16) * 80 + (kb + b_cb) * 2);
                ldsm4(sb + P1_B + so + bofs, bh);
#pragma unroll
                for (int na = 0; na < 2; na++) {
                    mma16816h(acc[0][bg * 2 + na], a0, bh + na * 2);
                    mma16816h(acc[1][bg * 2 + na], a1, bh + na * 2);
                }
            }
        }
        __syncthreads();
    }

#pragma unroll
    for (int am = 0; am < 2; am++) {
        int m0 = bm + wm * 32 + am * 16 + (l >> 2);
#pragma unroll
        for (int j = 0; j < 8; j++) {
            int n = bn + wn * 64 + j * 8 + 2 * (l & 3);
            float s0 = bih[n] + bhh[n];
            float s1 = bih[n + 1] + bhh[n + 1];
            float* c = acc[am][j];
            g_gx[(size_t)m0 * GG + n]           = c[0] + s0;
            g_gx[(size_t)m0 * GG + n + 1]       = c[1] + s1;
            g_gx[(size_t)(m0 + 8) * GG + n]     = c[2] + s0;
            g_gx[(size_t)(m0 + 8) * GG + n + 1] = c[3] + s1;
        }
    }
}

// ---------------------------------------------------------------------------
// Phase 2: persistent fp16 recurrence with PER-GROUP dataflow sync.
// 128 CTAs x 512 threads; CTA owns 8 h-columns (group = blockIdx/16 owns one
// 128-column chunk). 8 aggregated release words; consumers gate each chunk
// load on one word (coalesced 8-word peek + ballot), rotated consumption.
// ---------------------------------------------------------------------------
#define R_SW   0            // 32 rows x 2064B = 66048
#define R_SH   66048        // 8 stages x 17408B = 139264
#define R_HSTG 17408
#define R_SMEM 205312
// sg (2 planes x 64 x 36 floats = 18432B) aliases stages 0-1 (read only in
// chunk positions 0-1; all warps are past the position-7 sync before writes)

__global__ __launch_bounds__(512, 1) void lstm_mma_kernel(
    const float* __restrict__ c0, float* __restrict__ out)
{
    extern __shared__ __align__(16) char sm[];
    const uint32_t sb = smem_u32(sm);
    float* sg = (float*)(sm + R_SH);
    const int tid = threadIdx.x;
    const int wid = tid >> 5, l = tid & 31;
    const int j0 = blockIdx.x * 8;
    const int cg = blockIdx.x >> 4;      // own chunk group

    // --- read sync bases FIRST (replay-safe; monotonic counters) ---
    unsigned rb = 0;
    if (l < 8) rb = *(volatile unsigned*)&g_rel[l];   // per-lane release base
    unsigned rbmy = 0, cbmy = 0;
    if (tid == 0) {
        rbmy = *(volatile unsigned*)&g_rel[cg];
        cbmy = *(volatile unsigned*)&g_cnt[cg];
    }

    const __half* w16 = g_whh16 + (size_t)blockIdx.x * 32 * HH;

    // ---- Load W into SMEM once: 32 rows x 1024 fp16, row stride 2064B ----
    for (int cid = tid; cid < 4096; cid += 512) {
        int row = cid >> 7, seg = cid & 127;
        uint32_t sofs = (uint32_t)(row * 2064 + seg * 16);
        *(uint4*)(sm + R_SW + sofs) = *(const uint4*)(w16 + (size_t)row * HH + seg * 8);
    }

    // cell state: 1 elem/thread
    const int pb = tid >> 3, pjl = tid & 7;
    float c_reg = c0[(size_t)pb * HH + j0 + pjl];
    __syncthreads();

    // warp geometry: kh = K-half, w8 in 4m x 2n (warp tile m16 x n16)
    const int kh = wid >> 3, w8 = wid & 7;
    const int m0 = (w8 & 3) * 16, n0 = (w8 >> 2) * 16;
    const int a_r = m0 + (l & 7) + ((l >> 3) & 1) * 8;
    const int a_cb = ((l >> 4) & 1) * 8;
    const int b_r = n0 + (l & 7) + ((l >> 4) & 1) * 8;
    const int b_cb = ((l >> 3) & 1) * 8;

    const int hrow = tid >> 3, hseg = tid & 7;   // per chunk: 2 cp16/thread

    // warp-collective readiness peek: one coalesced 8-word read + ballot
    auto peek_mask = [&](unsigned t) -> unsigned {
        unsigned v = 0;
        if (l < 8) v = flag_acq(&g_rel[l]);
        bool ok = (l >= 8) || ((int)(v - (rb + t)) >= 0);
        return __ballot_sync(0xFFFFFFFFu, ok);
    };

    // initial gx prefetch (t = 0)
    float gpre[4];
    {
        const float* gr = g_gx + (size_t)pb * GG + j0 + pjl;
#pragma unroll
        for (int g = 0; g < 4; g++) gpre[g] = gr[g * HH];
    }

    for (int t = 0; t < TT; t++) {
        const __half* h16 = g_h16[t & 1];

        // ---- issue phase: per-chunk gating, rotated (own group first) ----
        unsigned m = 0xFFFFFFFFu;
        if (t > 0) m = peek_mask((unsigned)t);
#pragma unroll
        for (int c = 0; c < 8; c++) {
            const int grp = (cg + c) & 7;
            while (!((m >> grp) & 1u)) m = peek_mask((unsigned)t);
            const uint32_t so = R_SH + c * R_HSTG;
            const size_t base2 = (size_t)hrow * HH + grp * 128;
#pragma unroll
            for (int i = 0; i < 2; i++) {
                int seg = hseg + i * 8;
                cp16(sb + so + (uint32_t)(hrow * 272 + seg * 16),
                     h16 + base2 + seg * 8);
            }
            CP_COMMIT();
        }

        float acc[2][4];
#pragma unroll
        for (int na = 0; na < 2; na++)
#pragma unroll
            for (int q = 0; q < 4; q++) acc[na][q] = 0.f;

        // ---- drain + compute: one sync per chunk ----
#pragma unroll
        for (int c = 0; c < 8; c++) {
            cp_wait_dyn(7 - c);
            __syncthreads();
            const int grp = (cg + c) & 7;
            const uint32_t so = R_SH + c * R_HSTG;
#pragma unroll
            for (int kk = 0; kk < 64; kk += 16) {
                const int kb = kh * 64 + kk;
                uint32_t ah[4], bh[4];
                ldsm4(sb + so + (uint32_t)(a_r * 272 + (kb + a_cb) * 2), ah);
                ldsm4(sb + R_SW + (uint32_t)(b_r * 2064 + (grp * 128 + kb + b_cb) * 2), bh);
#pragma unroll
                for (int na = 0; na < 2; na++)
                    mma16816h(acc[na], ah, bh + na * 2);
            }
        }

        // prefetch next step's gx (hides DRAM latency under epilogue)
        float gnext[4];
        if (t < TT - 1) {
            const float* gr = g_gx + (size_t)(t + 1) * BB * GG
                              + (size_t)pb * GG + j0 + pjl;
#pragma unroll
            for (int g = 0; g < 4; g++) gnext[g] = gr[g * HH];
        }

        // stage partial D planes to SMEM (plane kh); safe: sg aliases stage
        // positions 0-1, last read at positions 0-1; writers passed pos-7 sync.
        {
            float* sgp = sg + kh * (64 * 36);
            int mm = m0 + (l >> 2);
#pragma unroll
            for (int na = 0; na < 2; na++) {
                int n = n0 + na * 8 + 2 * (l & 3);
                *(float2*)&sgp[mm * 36 + n]       = make_float2(acc[na][0], acc[na][1]);
                *(float2*)&sgp[(mm + 8) * 36 + n] = make_float2(acc[na][2], acc[na][3]);
            }
        }
        __syncthreads();

        // pointwise LSTM cell: 1 elem/thread
        float* h_out = out + (size_t)t * BB * HH;
        __half* nh16 = g_h16[(t + 1) & 1];
        {
            const float* s0 = sg + pb * 36;
            const float* s1 = sg + 64 * 36 + pb * 36;
            float gi = s0[pjl]      + s1[pjl]      + gpre[0];
            float gf = s0[8 + pjl]  + s1[8 + pjl]  + gpre[1];
            float gg = s0[16 + pjl] + s1[16 + pjl] + gpre[2];
            float go = s0[24 + pjl] + s1[24 + pjl] + gpre[3];
            float ig = 1.0f / (1.0f + __expf(-gi));
            float fg = 1.0f / (1.0f + __expf(-gf));
            float gv = tanhf(gg);
            float og = 1.0f / (1.0f + __expf(-go));
            float cn = fg * c_reg + ig * gv;
            float hn = og * tanhf(cn);
            c_reg = cn;
            size_t hoff = (size_t)pb * HH + j0 + pjl;
            h_out[hoff] = hn;
            nh16[hoff] = __float2half(hn);
            if (t == TT - 1) {
                out[(size_t)TT * BB * HH + hoff] = hn;
                out[(size_t)TT * BB * HH + BB * HH + hoff] = cn;
            }
        }
#pragma unroll
        for (int g = 0; g < 4; g++) gpre[g] = gnext[g];

        // ---- publish: fence + group counter; 16th arriver releases word ----
        if (t < TT - 1) {
            __threadfence();
            __syncthreads();
            if (tid == 0) {
                unsigned old = atomicAdd(&g_cnt[cg], 1u);
                if (old == cbmy + (unsigned)t * 16u + 15u) {
                    flag_rel(&g_rel[cg], rbmy + (unsigned)(t + 1));
                }
            }
        }
    }
}

extern "C" void kernel_launch(void* const* d_in, const int* in_sizes, int n_in,
                              void* d_out, int out_size)
{
    const float* x    = (const float*)d_in[0];
    const float* h0   = (const float*)d_in[1];
    const float* c0   = (const float*)d_in[2];
    const float* w_ih = (const float*)d_in[3];
    const float* b_ih = (const float*)d_in[4];
    const float* w_hh = (const float*)d_in[5];
    const float* b_hh = (const float*)d_in[6];
    float* out = (float*)d_out;
    (void)in_sizes; (void)n_in; (void)out_size;

    // Prep
    prep_x_kernel<<<(int)(((size_t)TT * BB * DD + 255) / 256), 256>>>(x);
    prep_wih_kernel<<<(GG * DD + 255) / 256, 256>>>(w_ih);
    prep_whh_kernel<<<(GG * HH + 255) / 256, 256>>>(w_hh);
    prep_h_kernel<<<(BB * HH + 255) / 256, 256>>>(h0);

    // Phase 1: input projection on tensor cores (fp16 single-term)
    cudaFuncSetAttribute(gemm_gx_mma,
                         cudaFuncAttributeMaxDynamicSharedMemorySize, P1_SMEM);
    dim3 g1(GG / 128, (TT * BB) / 128);
    gemm_gx_mma<<<g1, 256, P1_SMEM>>>(b_ih, b_hh);

    // Phase 2: persistent fp16 recurrence (per-group dataflow sync)
    cudaFuncSetAttribute(lstm_mma_kernel,
                         cudaFuncAttributeMaxDynamicSharedMemorySize, R_SMEM);
    lstm_mma_kernel<<<NCTA, 512, R_SMEM>>>(c0, out);
}

// round 14
// speedup vs baseline: 1.7236x; 1.2858x over previous
#include <cuda_runtime.h>
#include <cuda_bf16.h>
#include <cuda_fp16.h>
#include <math.h>
#include <stdint.h>

#define TT 512
#define BB 64
#define DD 1024
#define HH 1024
#define GG 4096
#define NCTA 128

// ---------------------------------------------------------------------------
// Device scratch (allocation-free rules: __device__ globals)
// ---------------------------------------------------------------------------
static __device__ float g_gx[(size_t)TT * BB * GG];        // input gates (+biases)
static __device__ __half g_x16[(size_t)TT * BB * DD];      // x fp16 (phase 1)
static __device__ __half g_wih16[GG * DD];                 // w_ih fp16 (phase 1)
static __device__ __half g_whh16[GG * HH];                 // w_hh fp16, CTA-tiled rows
// h fp16 ping-pong, GROUP-MAJOR + bank-swizzled:
// halfindex = grp*8192 + row*128 + ((seg ^ (row&7))<<3) + within,
//   where col = grp*128 + seg*8 + within  (seg 0..15, within 0..7)
static __device__ __align__(16) __half g_h16[2][8 * 8192];
static __device__ unsigned g_cnt[8];                       // per-group arrive counters (monotonic)
static __device__ unsigned g_rel[8];                       // per-group release words (monotonic)

// ---------------------------------------------------------------------------
// Baseline-PTX helpers (all sm_90-or-earlier baseline: compile for plain sm_103)
// ---------------------------------------------------------------------------
__device__ __forceinline__ uint32_t smem_u32(const void* p) {
    uint32_t a;
    asm("{ .reg .u64 t; cvta.to.shared.u64 t, %1; cvt.u32.u64 %0, t; }"
        : "=r"(a) : "l"(p));
    return a;
}
__device__ __forceinline__ void cp16(uint32_t dst, const void* src) {
    asm volatile("cp.async.cg.shared.global [%0], [%1], 16;" :: "r"(dst), "l"(src) : "memory");
}
#define CP_COMMIT() asm volatile("cp.async.commit_group;" ::: "memory")
#define CP_WAIT0()  asm volatile("cp.async.wait_group 0;" ::: "memory")
#define CP_WAIT1()  asm volatile("cp.async.wait_group 1;" ::: "memory")

__device__ __forceinline__ void ldsm4(uint32_t addr, uint32_t* r) {
    asm volatile("ldmatrix.sync.aligned.m8n8.x4.shared.b16 {%0,%1,%2,%3}, [%4];"
                 : "=r"(r[0]), "=r"(r[1]), "=r"(r[2]), "=r"(r[3]) : "r"(addr));
}
__device__ __forceinline__ void mma16816h(float* c, const uint32_t* a, const uint32_t* b) {
    asm volatile("mma.sync.aligned.m16n8k16.row.col.f32.f16.f16.f32 "
                 "{%0,%1,%2,%3}, {%4,%5,%6,%7}, {%8,%9}, {%0,%1,%2,%3};"
                 : "+f"(c[0]), "+f"(c[1]), "+f"(c[2]), "+f"(c[3])
                 : "r"(a[0]), "r"(a[1]), "r"(a[2]), "r"(a[3]), "r"(b[0]), "r"(b[1]));
}
__device__ __forceinline__ unsigned flag_acq(const unsigned* p) {
    unsigned v;
    asm volatile("ld.acquire.gpu.global.u32 %0, [%1];" : "=r"(v) : "l"(p) : "memory");
    return v;
}
__device__ __forceinline__ void flag_rel(unsigned* p, unsigned v) {
    asm volatile("st.release.gpu.global.u32 [%0], %1;" :: "l"(p), "r"(v) : "memory");
}
// mbarrier (sm_80/90 baseline)
#define MBAR_INIT(mb, n) \
    asm volatile("mbarrier.init.shared.b64 [%0], %1;" :: "r"((uint32_t)(mb)), "r"((uint32_t)(n)) : "memory")
#define MBAR_EXPECT_TX(mb, bytes) \
    asm volatile("mbarrier.arrive.expect_tx.shared.b64 _, [%0], %1;" :: "r"((uint32_t)(mb)), "r"((uint32_t)(bytes)) : "memory")
#define MBAR_WAIT_PARITY(mb, ph) do { \
    uint32_t _m = (uint32_t)(mb); uint32_t _p = (uint32_t)(ph); uint32_t _d; \
    asm volatile("{\n\t.reg .pred p;\n\t" \
        "mbarrier.try_wait.parity.acquire.cta.shared::cta.b64 p, [%1], %2;\n\t" \
        "selp.b32 %0, 1, 0, p;\n\t}" : "=r"(_d) : "r"(_m), "r"(_p) : "memory"); \
    if (!_d) { \
        asm volatile("{\n\t.reg .pred P1;\n\tWL_%=:\n\t" \
            "mbarrier.try_wait.parity.acquire.cta.shared::cta.b64 P1, [%0], %1, 0x989680;\n\t" \
            "@P1 bra.uni WD_%=;\n\tbra.uni WL_%=;\n\tWD_%=:\n\t}" \
            :: "r"(_m), "r"(_p) : "memory"); \
    } } while (0)
// 1D bulk DMA global->shared with mbarrier completion (sm_90 baseline)
__device__ __forceinline__ void bulk_g2s(uint32_t dst, const void* src, uint32_t bytes,
                                         uint32_t mbar) {
    asm volatile("cp.async.bulk.shared::cluster.global.mbarrier::complete_tx::bytes "
                 "[%0], [%1], %2, [%3];"
                 :: "r"(dst), "l"(src), "r"(bytes), "r"(mbar) : "memory");
}

// ---------------------------------------------------------------------------
// Prep kernels
// ---------------------------------------------------------------------------
__global__ void prep_x_kernel(const float* __restrict__ x) {
    size_t idx = (size_t)blockIdx.x * blockDim.x + threadIdx.x;
    if (idx >= (size_t)TT * BB * DD) return;
    g_x16[idx] = __float2half(x[idx]);
}
__global__ void prep_wih_kernel(const float* __restrict__ w) {
    int idx = blockIdx.x * blockDim.x + threadIdx.x;
    if (idx >= GG * DD) return;
    g_wih16[idx] = __float2half(w[idx]);
}
// w_hh reorder to fp16: CTA cta owns 32 rows r = g*8+jl <-> in_row = g*1024+cta*8+jl
__global__ void prep_whh_kernel(const float* __restrict__ w) {
    int idx = blockIdx.x * blockDim.x + threadIdx.x;
    if (idx >= GG * HH) return;
    int orow = idx >> 10, k = idx & 1023;
    int cta = orow >> 5, r = orow & 31;
    int g = r >> 3, jl = r & 7;
    int in_row = (g << 10) + (cta << 3) + jl;
    g_whh16[idx] = __float2half(w[(size_t)in_row * HH + k]);
}
__global__ void prep_h_kernel(const float* __restrict__ h0) {
    int idx = blockIdx.x * blockDim.x + threadIdx.x;
    if (idx >= BB * HH) return;
    int row = idx >> 10, col = idx & 1023;
    int grp = col >> 7, lc = col & 127;
    int seg = lc >> 3, wthn = lc & 7;
    int hix = grp * 8192 + row * 128 + (((seg ^ (row & 7))) << 3) + wthn;
    g_h16[0][hix] = __float2half(h0[idx]);
}

// ---------------------------------------------------------------------------
// Phase 1: gates_x = x @ w_ih^T + b_ih + b_hh  via mma.sync fp16 single-term.
// (unchanged from round 12/13)
// ---------------------------------------------------------------------------
#define P1_STG 10240      // 128 rows x 80B
#define P1_A 0
#define P1_B 20480
#define P1_SMEM 40960

__global__ __launch_bounds__(256, 2) void gemm_gx_mma(
    const float* __restrict__ bih, const float* __restrict__ bhh)
{
    extern __shared__ __align__(16) char sm[];
    const uint32_t sb = smem_u32(sm);
    const int tid = threadIdx.x;
    const int wid = tid >> 5, l = tid & 31;
    const int bm = blockIdx.y * 128, bn = blockIdx.x * 128;
    const int wm = wid & 3, wn = wid >> 2;

    const int a_r = wm * 32 + (l & 7) + ((l >> 3) & 1) * 8;
    const int a_cb = ((l >> 4) & 1) * 8;
    const int b_r = wn * 64 + (l & 7) + ((l >> 4) & 1) * 8;
    const int b_cb = ((l >> 3) & 1) * 8;

    float acc[2][8][4];
#pragma unroll
    for (int i = 0; i < 2; i++)
#pragma unroll
        for (int j = 0; j < 8; j++)
#pragma unroll
            for (int q = 0; q < 4; q++) acc[i][j][q] = 0.f;

    auto load_stage = [&](int c, int st) {
        const uint32_t so = st * P1_STG;
        size_t koff = (size_t)c * 32;
#pragma unroll
        for (int i = 0; i < 2; i++) {
            int idx = tid + (i << 8);
            int row = idx >> 2, seg = idx & 3;
            uint32_t sofs = (uint32_t)(row * 80 + seg * 16);
            cp16(sb + P1_A + so + sofs, g_x16 + (size_t)(bm + row) * DD + koff + seg * 8);
            cp16(sb + P1_B + so + sofs, g_wih16 + (size_t)(bn + row) * DD + koff + seg * 8);
        }
        CP_COMMIT();
    };

    load_stage(0, 0);

    for (int c = 0; c < 32; c++) {
        if (c < 31) load_stage(c + 1, (c + 1) & 1);
        if (c < 31) { CP_WAIT1(); } else { CP_WAIT0(); }
        __syncthreads();
        const uint32_t so = (c & 1) * P1_STG;
#pragma unroll
        for (int kb = 0; kb < 32; kb += 16) {
            uint32_t a0[4], a1[4];
            {
                uint32_t aofs = (uint32_t)((a_r) * 80 + (kb + a_cb) * 2);
                ldsm4(sb + P1_A + so + aofs, a0);
                ldsm4(sb + P1_A + so + aofs + 16 * 80, a1);
            }
#pragma unroll
            for (int bg = 0; bg < 4; bg++) {
                uint32_t bh[4];
                uint32_t bofs = (uint32_t)((b_r + bg * 16) * 80 + (kb + b_cb) * 2);
                ldsm4(sb + P1_B + so + bofs, bh);
#pragma unroll
                for (int na = 0; na < 2; na++) {
                    mma16816h(acc[0][bg * 2 + na], a0, bh + na * 2);
                    mma16816h(acc[1][bg * 2 + na], a1, bh + na * 2);
                }
            }
        }
        __syncthreads();
    }

#pragma unroll
    for (int am = 0; am < 2; am++) {
        int m0 = bm + wm * 32 + am * 16 + (l >> 2);
#pragma unroll
        for (int j = 0; j < 8; j++) {
            int n = bn + wn * 64 + j * 8 + 2 * (l & 3);
            float s0 = bih[n] + bhh[n];
            float s1 = bih[n + 1] + bhh[n + 1];
            float* c = acc[am][j];
            g_gx[(size_t)m0 * GG + n]           = c[0] + s0;
            g_gx[(size_t)m0 * GG + n + 1]       = c[1] + s1;
            g_gx[(size_t)(m0 + 8) * GG + n]     = c[2] + s0;
            g_gx[(size_t)(m0 + 8) * GG + n + 1] = c[3] + s1;
        }
    }
}

// ---------------------------------------------------------------------------
// Phase 2: persistent fp16 recurrence. h moves via cp.async.bulk (1 DMA per
// 16KB group block) completed on per-group mbarriers -> zero per-thread load
// issue, no per-chunk CTA syncs. Per-group dataflow flags gate the DMAs.
// 128 CTAs x 512 threads. CTA: D[64 batch x 32 gate-rows], K=1024.
// ---------------------------------------------------------------------------
#define R_SW   0            // 32 rows x 2064B = 66048
#define R_SH   66048        // 8 stages x 16384B = 131072
#define R_HSTG 16384
#define R_SG   197120       // 2 planes x 64 x 36 floats = 18432
#define R_MB   215552       // 8 mbarriers x 8B
#define R_SMEM 215680

__global__ __launch_bounds__(512, 1) void lstm_mma_kernel(
    const float* __restrict__ c0, float* __restrict__ out)
{
    extern __shared__ __align__(16) char sm[];
    const uint32_t sb = smem_u32(sm);
    float* sg = (float*)(sm + R_SG);
    const int tid = threadIdx.x;
    const int wid = tid >> 5, l = tid & 31;
    const int j0 = blockIdx.x * 8;
    const int cg = blockIdx.x >> 4;      // own chunk group

    // --- read sync bases FIRST (replay-safe; monotonic counters) ---
    unsigned rb = 0;
    if (l < 8) rb = *(volatile unsigned*)&g_rel[l];
    unsigned rbmy = 0, cbmy = 0;
    if (tid == 0) {
        rbmy = *(volatile unsigned*)&g_rel[cg];
        cbmy = *(volatile unsigned*)&g_cnt[cg];
    }

    const __half* w16 = g_whh16 + (size_t)blockIdx.x * 32 * HH;

    // ---- Load W into SMEM once: 32 rows x 1024 fp16, row stride 2064B ----
    for (int cid = tid; cid < 4096; cid += 512) {
        int row = cid >> 7, seg = cid & 127;
        uint32_t sofs = (uint32_t)(row * 2064 + seg * 16);
        *(uint4*)(sm + R_SW + sofs) = *(const uint4*)(w16 + (size_t)row * HH + seg * 8);
    }

    // mbarrier init (count 1: one expect_tx per step per group)
    if (tid == 0) {
#pragma unroll
        for (int i = 0; i < 8; i++) MBAR_INIT(sb + R_MB + i * 8, 1);
    }

    // cell state: 1 elem/thread
    const int pb = tid >> 3, pjl = tid & 7;
    float c_reg = c0[(size_t)pb * HH + j0 + pjl];
    __syncthreads();

    // warp geometry: kh = K-half, w8 in 4m x 2n (warp tile m16 x n16)
    const int kh = wid >> 3, w8 = wid & 7;
    const int m0 = (w8 & 3) * 16, n0 = (w8 >> 2) * 16;
    const int a_r = m0 + (l & 7) + ((l >> 3) & 1) * 8;
    const int a_cb = ((l >> 4) & 1) * 8;
    const int b_r = n0 + (l & 7) + ((l >> 4) & 1) * 8;
    const int b_cb = ((l >> 3) & 1) * 8;
    const int a_sw = (a_r & 7);           // swizzle key for h reads

    // pointwise write geometry into swizzled group-major h
    const int seg_c = blockIdx.x & 15;    // (j0&127)>>3
    const int h_wix = cg * 8192 + pb * 128 + ((seg_c ^ (pb & 7)) << 3) + pjl;

    // warp-collective readiness peek (warp 0 only)
    auto peek_mask = [&](unsigned t) -> unsigned {
        unsigned v = 0;
        if (l < 8) v = flag_acq(&g_rel[l]);
        bool ok = (l >= 8) || ((int)(v - (rb + t)) >= 0);
        return __ballot_sync(0xFFFFFFFFu, ok);
    };

    // initial gx prefetch (t = 0)
    float gpre[4];
    {
        const float* gr = g_gx + (size_t)pb * GG + j0 + pjl;
#pragma unroll
        for (int g = 0; g < 4; g++) gpre[g] = gr[g * HH];
    }

    for (int t = 0; t < TT; t++) {
        const __half* h16 = g_h16[t & 1];

        // ---- warp 0: gate + issue 8 bulk DMAs (rotated, own group first) ----
        if (wid == 0) {
            unsigned m = 0xFFFFFFFFu;
            if (t > 0) m = peek_mask((unsigned)t);
#pragma unroll
            for (int c = 0; c < 8; c++) {
                const int grp = (cg + c) & 7;
                while (!((m >> grp) & 1u)) m = peek_mask((unsigned)t);
                if (l == 0) {
                    uint32_t mb = sb + R_MB + c * 8;
                    MBAR_EXPECT_TX(mb, R_HSTG);
                    bulk_g2s(sb + R_SH + c * R_HSTG, h16 + grp * 8192, R_HSTG, mb);
                }
            }
        }

        float acc[2][4];
#pragma unroll
        for (int na = 0; na < 2; na++)
#pragma unroll
            for (int q = 0; q < 4; q++) acc[na][q] = 0.f;

        // ---- compute: warps wait per-group mbarriers independently ----
#pragma unroll
        for (int c = 0; c < 8; c++) {
            MBAR_WAIT_PARITY(sb + R_MB + c * 8, t & 1);
            const int grp = (cg + c) & 7;
            const uint32_t so = R_SH + c * R_HSTG;
#pragma unroll
            for (int kk = 0; kk < 64; kk += 16) {
                const int kb = kh * 64 + kk;
                uint32_t ah[4], bh[4];
                int seg = (kb + a_cb) >> 3;
                ldsm4(so + sb + (uint32_t)(a_r * 256 + ((seg ^ a_sw) << 4)), ah);
                ldsm4(sb + R_SW + (uint32_t)(b_r * 2064 + (grp * 128 + kb + b_cb) * 2), bh);
#pragma unroll
                for (int na = 0; na < 2; na++)
                    mma16816h(acc[na], ah, bh + na * 2);
            }
        }

        // prefetch next step's gx
        float gnext[4];
        if (t < TT - 1) {
            const float* gr = g_gx + (size_t)(t + 1) * BB * GG
                              + (size_t)pb * GG + j0 + pjl;
#pragma unroll
            for (int g = 0; g < 4; g++) gnext[g] = gr[g * HH];
        }

        // stage partial D planes (separate sg region; no aliasing)
        {
            float* sgp = sg + kh * (64 * 36);
            int mm = m0 + (l >> 2);
#pragma unroll
            for (int na = 0; na < 2; na++) {
                int n = n0 + na * 8 + 2 * (l & 3);
                *(float2*)&sgp[mm * 36 + n]       = make_float2(acc[na][0], acc[na][1]);
                *(float2*)&sgp[(mm + 8) * 36 + n] = make_float2(acc[na][2], acc[na][3]);
            }
        }
        __syncthreads();

        // pointwise LSTM cell: 1 elem/thread
        float* h_out = out + (size_t)t * BB * HH;
        __half* nh16 = g_h16[(t + 1) & 1];
        {
            const float* s0 = sg + pb * 36;
            const float* s1 = sg + 64 * 36 + pb * 36;
            float gi = s0[pjl]      + s1[pjl]      + gpre[0];
            float gf = s0[8 + pjl]  + s1[8 + pjl]  + gpre[1];
            float gg = s0[16 + pjl] + s1[16 + pjl] + gpre[2];
            float go = s0[24 + pjl] + s1[24 + pjl] + gpre[3];
            float ig = 1.0f / (1.0f + __expf(-gi));
            float fg = 1.0f / (1.0f + __expf(-gf));
            float gv = tanhf(gg);
            float og = 1.0f / (1.0f + __expf(-go));
            float cn = fg * c_reg + ig * gv;
            float hn = og * tanhf(cn);
            c_reg = cn;
            size_t hoff = (size_t)pb * HH + j0 + pjl;
            h_out[hoff] = hn;
            nh16[h_wix] = __float2half(hn);
            if (t == TT - 1) {
                out[(size_t)TT * BB * HH + hoff] = hn;
                out[(size_t)TT * BB * HH + BB * HH + hoff] = cn;
            }
        }
#pragma unroll
        for (int g = 0; g < 4; g++) gpre[g] = gnext[g];

        // ---- publish: fence + group counter; 16th arriver releases word ----
        if (t < TT - 1) {
            __threadfence();
            __syncthreads();
            if (tid == 0) {
                unsigned old = atomicAdd(&g_cnt[cg], 1u);
                if (old == cbmy + (unsigned)t * 16u + 15u) {
                    flag_rel(&g_rel[cg], rbmy + (unsigned)(t + 1));
                }
            }
        }
    }
}

extern "C" void kernel_launch(void* const* d_in, const int* in_sizes, int n_in,
                              void* d_out, int out_size)
{
    const float* x    = (const float*)d_in[0];
    const float* h0   = (const float*)d_in[1];
    const float* c0   = (const float*)d_in[2];
    const float* w_ih = (const float*)d_in[3];
    const float* b_ih = (const float*)d_in[4];
    const float* w_hh = (const float*)d_in[5];
    const float* b_hh = (const float*)d_in[6];
    float* out = (float*)d_out;
    (void)in_sizes; (void)n_in; (void)out_size;

    // Prep
    prep_x_kernel<<<(int)(((size_t)TT * BB * DD + 255) / 256), 256>>>(x);
    prep_wih_kernel<<<(GG * DD + 255) / 256, 256>>>(w_ih);
    prep_whh_kernel<<<(GG * HH + 255) / 256, 256>>>(w_hh);
    prep_h_kernel<<<(BB * HH + 255) / 256, 256>>>(h0);

    // Phase 1: input projection on tensor cores (fp16 single-term)
    cudaFuncSetAttribute(gemm_gx_mma,
                         cudaFuncAttributeMaxDynamicSharedMemorySize, P1_SMEM);
    dim3 g1(GG / 128, (TT * BB) / 128);
    gemm_gx_mma<<<g1, 256, P1_SMEM>>>(b_ih, b_hh);

    // Phase 2: persistent fp16 recurrence (bulk-DMA h + mbarrier completion)
    cudaFuncSetAttribute(lstm_mma_kernel,
                         cudaFuncAttributeMaxDynamicSharedMemorySize, R_SMEM);
    lstm_mma_kernel<<<NCTA, 512, R_SMEM>>>(c0, out);
}